// round 16
// baseline (speedup 1.0000x reference)
#include <cuda_runtime.h>
#include <cuda_fp16.h>
#include <cstdint>

#define Ss 2048
#define Dd 64
constexpr int BH  = 32;
constexpr int QT  = 64;            // q rows per CTA
constexpr int KT  = 128;           // k cols per tile
constexpr int NTH = 256;           // 8 warps: 4 row-groups x 2 col-halves
constexpr int NT  = Ss / KT;       // 16
constexpr long long OUT_ELEMS = (long long)BH * Ss * Dd;
constexpr long long ATT_ELEMS = (long long)BH * Ss * (long long)Ss;

// static device scratch
__device__ __align__(256) __half g_qh[(size_t)BH * Ss * Dd];   // pre-scaled by log2e/8
__device__ __align__(256) __half g_kh[(size_t)BH * Ss * Dd];
__device__ __align__(256) uint32_t g_mb[(size_t)2 * Ss * Ss / 32];   // bit-packed mask
__device__ __align__(256) uint32_t g_u32[(size_t)ATT_ELEMS / 2];     // u relay, fragment layout
__device__ __align__(256) uint4 g_vf[(size_t)BH * 128 * 4 * 32];     // V in B-fragment layout (8MB)

// smem layout (bytes)
constexpr int OFF_RED = 0;                        // srows[2][64] + srinv[64]
constexpr int OFF_Q   = 1024;                     // 64 x 144 = 9216
constexpr int KSTG    = 128 * 144;                // 18432
constexpr int OFF_K   = 10240;                    // P1: 2 stages -> 47104; P2 ost overlay
constexpr int SMEM_BYTES = 47104;                 // 3 CTAs/SM

__device__ __forceinline__ uint32_t smem_u32(const void* p) {
    uint32_t a;
    asm("{ .reg .u64 t; cvta.to.shared.u64 t, %1; cvt.u32.u64 %0, t; }" : "=r"(a) : "l"(p));
    return a;
}
__device__ __forceinline__ void ldsm4(uint32_t r[4], uint32_t a) {
    asm volatile("ldmatrix.sync.aligned.m8n8.x4.shared.b16 {%0,%1,%2,%3}, [%4];"
                 : "=r"(r[0]), "=r"(r[1]), "=r"(r[2]), "=r"(r[3]) : "r"(a) : "memory");
}
__device__ __forceinline__ void mma16816(float c[4], const uint32_t a[4], uint32_t b0, uint32_t b1) {
    asm volatile(
        "mma.sync.aligned.m16n8k16.row.col.f32.f16.f16.f32 "
        "{%0,%1,%2,%3}, {%4,%5,%6,%7}, {%8,%9}, {%0,%1,%2,%3};"
        : "+f"(c[0]), "+f"(c[1]), "+f"(c[2]), "+f"(c[3])
        : "r"(a[0]), "r"(a[1]), "r"(a[2]), "r"(a[3]), "r"(b0), "r"(b1));
}
__device__ __forceinline__ uint32_t packh2(float x, float y) {
    __half2 h = __floats2half2_rn(x, y);
    return *(uint32_t*)&h;
}
__device__ __forceinline__ float ex2f(float x) {
    float r; asm("ex2.approx.f32 %0, %1;" : "=f"(r) : "f"(x)); return r;
}
#define CPA16(dst, src) asm volatile("cp.async.cg.shared.global [%0], [%1], 16;" :: "r"(dst), "l"(src))
#define CP_COMMIT()     asm volatile("cp.async.commit_group;" ::: "memory")
#define CP_WAIT0()      asm volatile("cp.async.wait_group 0;" ::: "memory")
#define STG64CS(p, x, y) \
    asm volatile("st.global.cs.v2.f32 [%0], {%1,%2};" :: "l"(p), "f"(x), "f"(y) : "memory")

constexpr int QK_BLOCKS   = 2 * (BH * Ss * Dd / 4) / 256;       // 8192
constexpr int VF_BLOCKS   = (BH * 128 * 4 * 32) / 256;          // 2048
constexpr int MBIT_BLOCKS = (2 * Ss * Ss / 32) / 256;           // 1024
constexpr float QSCALE = 0.18033688011112042f;                  // log2(e)/8

__global__ void __launch_bounds__(256) cvt_all(const float* __restrict__ Q,
                                               const float* __restrict__ K,
                                               const float* __restrict__ V,
                                               const int* __restrict__ M)
{
    if (blockIdx.x < QK_BLOCKS) {
        const int n4 = BH * Ss * Dd / 4;
        int id = blockIdx.x * 256 + threadIdx.x;
        const float* src; __half* dst; float s;
        int i = id;
        if (id < n4) { src = Q; dst = g_qh; s = QSCALE; }
        else         { src = K; dst = g_kh; s = 1.f; i -= n4; }
        float4 v = ((const float4*)src)[i];
        uint2 u; u.x = packh2(v.x * s, v.y * s); u.y = packh2(v.z * s, v.w * s);
        ((uint2*)dst)[i] = u;
    } else if (blockIdx.x < QK_BLOCKS + VF_BLOCKS) {
        // V -> B-fragment layout: vid = ((bh*128 + Kc)*4 + np)*32 + lane
        int vid = (blockIdx.x - QK_BLOCKS) * 256 + threadIdx.x;
        int lane = vid & 31, np = (vid >> 5) & 3, Kc = (vid >> 7) & 127, bhv = vid >> 14;
        int tgv = lane & 3, gv = lane >> 2;
        const float* vs = V + ((size_t)bhv * Ss + Kc * 16) * Dd;
        int d0 = np * 16 + gv;
        int r  = 2 * tgv;
        float v00a = vs[r * 64 + d0],        v01a = vs[(r + 1) * 64 + d0];
        float v10a = vs[(r + 8) * 64 + d0],  v11a = vs[(r + 9) * 64 + d0];
        float v00b = vs[r * 64 + d0 + 8],       v01b = vs[(r + 1) * 64 + d0 + 8];
        float v10b = vs[(r + 8) * 64 + d0 + 8], v11b = vs[(r + 9) * 64 + d0 + 8];
        uint4 o;
        o.x = packh2(v00a, v01a); o.y = packh2(v10a, v11a);
        o.z = packh2(v00b, v01b); o.w = packh2(v10b, v11b);
        g_vf[vid] = o;
    } else {
        int gid = (blockIdx.x - QK_BLOCKS - VF_BLOCKS) * 256 + threadIdx.x;
        const int4* mp = (const int4*)M + (size_t)gid * 8;
        uint32_t bits = 0;
        #pragma unroll
        for (int j = 0; j < 8; j++) {
            int4 m = mp[j];
            bits |= (m.x ? 1u : 0u) << (4 * j);
            bits |= (m.y ? 1u : 0u) << (4 * j + 1);
            bits |= (m.z ? 1u : 0u) << (4 * j + 2);
            bits |= (m.w ? 1u : 0u) << (4 * j + 3);
        }
        g_mb[gid] = bits;
    }
}

extern __shared__ __align__(16) char sm[];

// ---------------- pass 1 tile body (unchanged from R13) ----------------
#define P1_BODY(T, CUR, NXT) do {                                          \
    if ((T) + 1 < NT) {                                                    \
        CPA16(kdst##NXT,         kpre);                                    \
        CPA16(kdst##NXT +  4608, kpre + 2048);                             \
        CPA16(kdst##NXT +  9216, kpre + 4096);                             \
        CPA16(kdst##NXT + 13824, kpre + 6144);                             \
        CP_COMMIT();                                                       \
        kpre += (size_t)KT * Dd;                                           \
        mn0 = __ldg(mr0 + 2 * ((T) + 1));                                  \
        mn1 = __ldg(mr1 + 2 * ((T) + 1));                                  \
    }                                                                      \
    _Pragma("unroll") for (int ch = 0; ch < 2; ch++) {                     \
        float c4[4][4];                                                    \
        _Pragma("unroll") for (int j = 0; j < 4; j++) {                    \
            c4[j][0] = 0.f; c4[j][1] = 0.f; c4[j][2] = 0.f; c4[j][3] = 0.f; } \
        _Pragma("unroll") for (int kc = 0; kc < 4; kc++)                   \
            _Pragma("unroll") for (int j = 0; j < 2; j++) {                \
                uint32_t bf[4];                                            \
                ldsm4(bf, kfr##CUR + (2 * ch + j) * 2304 + kc * 32);       \
                mma16816(c4[2 * j],     aQ[kc], bf[0], bf[1]);             \
                mma16816(c4[2 * j + 1], aQ[kc], bf[2], bf[3]);             \
            }                                                              \
        uint32_t ul[4], uh[4];                                             \
        _Pragma("unroll") for (int j = 0; j < 4; j++) {                    \
            const int p = 8 * (4 * ch + j) + 2 * tg;                       \
            uint32_t b0 = (uint32_t)(mc0 >> p), b1 = (uint32_t)(mc1 >> p); \
            float u0 = (b0 & 1u) ? ex2f(c4[j][0]) : 0.f;                   \
            float u1 = (b0 & 2u) ? ex2f(c4[j][1]) : 0.f;                   \
            float u2 = (b1 & 1u) ? ex2f(c4[j][2]) : 0.f;                   \
            float u3 = (b1 & 2u) ? ex2f(c4[j][3]) : 0.f;                   \
            rs0 += u0 + u1; rs1 += u2 + u3;                                \
            ul[j] = packh2(u0, u1); uh[j] = packh2(u2, u3);                \
        }                                                                  \
        *(uint4*)(ut + (2 * ch) * 1024)     = make_uint4(ul[0], uh[0], ul[1], uh[1]); \
        *(uint4*)(ut + (2 * ch + 1) * 1024) = make_uint4(ul[2], uh[2], ul[3], uh[3]); \
    }                                                                      \
    ut += 4096;                                                            \
    mc0 = mn0; mc1 = mn1;                                                  \
    if ((T) + 1 < NT) { CP_WAIT0(); __syncthreads(); }                     \
} while (0)

__global__ void __launch_bounds__(NTH, 3)
attn_kernel(float* __restrict__ out, float* __restrict__ att)
{
    const int tid  = threadIdx.x;
    const int lane = tid & 31;
    const int warp = tid >> 5;
    const int g    = lane >> 2;
    const int tg   = lane & 3;
    const int lm   = lane >> 3;
    const int ll   = lane & 7;
    const int rgrp = warp & 3;         // q-row group (16 rows)
    const int h    = warp >> 2;        // k-col half (64 cols)

    const int qblk = blockIdx.x;
    const int q0 = qblk * QT;
    const int bh = blockIdx.y;
    const int b  = bh >> 4;

    const uint32_t smb = smem_u32(sm);
    float* srows = (float*)(sm + OFF_RED);          // [2][64]
    float* srinv = (float*)(sm + OFF_RED + 512);    // [64]

    const __half* qsrc = g_qh + ((size_t)bh * Ss + q0) * Dd;
    const __half* ksrc = g_kh + (size_t)bh * Ss * Dd;
    float* attg = att ? (att + (size_t)bh * Ss * (size_t)Ss) : nullptr;

    const int r0 = rgrp * 16 + g;
    const int r1 = r0 + 8;

    // bit-mask row pointers
    const unsigned long long* mb64 = (const unsigned long long*)g_mb;
    const unsigned long long* mr0 = mb64 + ((size_t)b * Ss + q0 + r0) * 32 + h;
    const unsigned long long* mr1 = mr0 + 8 * 32;

    // u relay pointers (fragment layout: [tile][slot(4)][tid][16B])
    uint32_t* ut = g_u32 + (((size_t)bh * 32 + qblk) * 16) * 4096 + tid * 4;
    const char* upr = (const char*)(g_u32 + (((size_t)bh * 32 + qblk) * 16) * 4096) + tid * 16;

    // per-thread cp.async addresses
    const int lr_ = tid >> 3, lc = tid & 7;
    const uint32_t kdstA = smb + OFF_K + lr_ * 144 + lc * 16;
    const uint32_t kdstB = kdstA + KSTG;
    const __half* ksrcT = ksrc + lr_ * 64 + lc * 8;

    // fragment bases
    const uint32_t qfr  = smb + OFF_Q + (uint32_t)((rgrp * 16 + (lm & 1) * 8 + ll) * 144 + (lm >> 1) * 16);
    const uint32_t kfrA = smb + OFF_K + (uint32_t)((h * 64 + (lm >> 1) * 8 + ll) * 144 + (lm & 1) * 16);
    const uint32_t kfrB = kfrA + KSTG;

    // ---- pass-1 prologue: Q + K0 ----
    CPA16(smb + OFF_Q + lr_ * 144 + lc * 16, qsrc + lr_ * 64 + lc * 8);
    CPA16(smb + OFF_Q + (lr_ + 32) * 144 + lc * 16, qsrc + (lr_ + 32) * 64 + lc * 8);
    CPA16(kdstA,         ksrcT);
    CPA16(kdstA +  4608, ksrcT + 2048);
    CPA16(kdstA +  9216, ksrcT + 4096);
    CPA16(kdstA + 13824, ksrcT + 6144);
    CP_COMMIT();
    unsigned long long mc0 = __ldg(mr0), mc1 = __ldg(mr1), mn0 = 0, mn1 = 0;
    CP_WAIT0(); __syncthreads();

    uint32_t aQ[4][4];
    #pragma unroll
    for (int kc = 0; kc < 4; kc++) ldsm4(aQ[kc], qfr + kc * 32);

    // ================= PASS 1: row sums + u relay store =================
    float rs0 = 0.f, rs1 = 0.f;
    {
        const __half* kpre = ksrcT + (size_t)KT * Dd;
        #pragma unroll 1
        for (int t2 = 0; t2 < NT; t2 += 2) {
            P1_BODY(t2,     A, B);
            P1_BODY(t2 + 1, B, A);
        }
    }

    // reduce quad lanes, then the 2 col-halves; reciprocals
    rs0 += __shfl_xor_sync(0xffffffffu, rs0, 1); rs0 += __shfl_xor_sync(0xffffffffu, rs0, 2);
    rs1 += __shfl_xor_sync(0xffffffffu, rs1, 1); rs1 += __shfl_xor_sync(0xffffffffu, rs1, 2);
    if (tg == 0) { srows[h * 64 + r0] = rs0; srows[h * 64 + r1] = rs1; }
    __syncthreads();
    if (tid < 64) {
        float s = srows[tid] + srows[64 + tid];
        srinv[tid] = (s > 0.f) ? (1.0f / s) : 0.f;
    }
    __syncthreads();
    const float rv0 = srinv[r0];
    const float rv1 = srinv[r1];

    // ================= PASS 2: smem-free PV + scaled att writeout =================
    float o[8][4];
    #pragma unroll
    for (int j = 0; j < 8; j++) { o[j][0] = 0.f; o[j][1] = 0.f; o[j][2] = 0.f; o[j][3] = 0.f; }

    {
        // V fragments: g_vf[((bh*128 + Kc)*4 + np)*32 + lane], Kc = t*8 + h*4 + kc
        const uint4* vfb = g_vf + (((size_t)bh * 128 + h * 4) * 4) * 32 + lane;
        float* ar = attg ? (attg + (size_t)(q0 + r0) * Ss + h * 64 + 2 * tg) : nullptr;
        #pragma unroll 1
        for (int t = 0; t < NT; t++) {
            uint4 ua[4];
            ua[0] = __ldg((const uint4*)(upr));
            ua[1] = __ldg((const uint4*)(upr + 4096));
            ua[2] = __ldg((const uint4*)(upr + 8192));
            ua[3] = __ldg((const uint4*)(upr + 12288));
            upr += 16384;
            const uint4* vft = vfb + (size_t)t * 8 * 4 * 32;
            #pragma unroll
            for (int kc = 0; kc < 4; kc++) {
                uint32_t a[4] = { ua[kc].x, ua[kc].y, ua[kc].z, ua[kc].w };
                const uint4* vf = vft + kc * 4 * 32;
                #pragma unroll
                for (int np = 0; np < 4; np++) {
                    uint4 bf = __ldg(vf + np * 32);
                    mma16816(o[2 * np],     a, bf.x, bf.y);
                    mma16816(o[2 * np + 1], a, bf.z, bf.w);
                }
                if (ar) {
                    float2 f0 = __half22float2(*(__half2*)&a[0]);
                    float2 f1 = __half22float2(*(__half2*)&a[1]);
                    float2 f2 = __half22float2(*(__half2*)&a[2]);
                    float2 f3 = __half22float2(*(__half2*)&a[3]);
                    STG64CS(ar + 16 * kc,              f0.x * rv0, f0.y * rv0);
                    STG64CS(ar + 8 * Ss + 16 * kc,     f1.x * rv1, f1.y * rv1);
                    STG64CS(ar + 16 * kc + 8,          f2.x * rv0, f2.y * rv0);
                    STG64CS(ar + 8 * Ss + 16 * kc + 8, f3.x * rv1, f3.y * rv1);
                }
            }
            if (ar) ar += KT;
        }
    }

    // ---- combine the two k-halves of O via smem (reuse K area), scale, write ----
    __syncthreads();
    float* ost = (float*)(sm + OFF_K);            // [64][66]
    if (h == 1) {
        #pragma unroll
        for (int j = 0; j < 8; j++) {
            *(float2*)&ost[r0 * 66 + 8 * j + 2 * tg] = make_float2(o[j][0], o[j][1]);
            *(float2*)&ost[r1 * 66 + 8 * j + 2 * tg] = make_float2(o[j][2], o[j][3]);
        }
    }
    __syncthreads();
    if (out && h == 0) {
        float* og0 = out + ((size_t)bh * Ss + q0 + r0) * Dd;
        float* og1 = out + ((size_t)bh * Ss + q0 + r1) * Dd;
        #pragma unroll
        for (int j = 0; j < 8; j++) {
            float2 s0 = *(float2*)&ost[r0 * 66 + 8 * j + 2 * tg];
            float2 s1 = *(float2*)&ost[r1 * 66 + 8 * j + 2 * tg];
            *(float2*)(og0 + 8 * j + 2 * tg) = make_float2((o[j][0] + s0.x) * rv0, (o[j][1] + s0.y) * rv0);
            *(float2*)(og1 + 8 * j + 2 * tg) = make_float2((o[j][2] + s1.x) * rv1, (o[j][3] + s1.y) * rv1);
        }
    }
}

extern "C" void kernel_launch(void* const* d_in, const int* in_sizes, int n_in,
                              void* d_out, int out_size)
{
    (void)in_sizes; (void)n_in;
    const float* Q = (const float*)d_in[0];
    const float* K = (const float*)d_in[1];
    const float* V = (const float*)d_in[2];
    const int*   M = (const int*)d_in[3];

    float* outp = nullptr;
    float* attp = nullptr;
    long long os = (long long)out_size;
    if (os >= OUT_ELEMS + ATT_ELEMS) {
        outp = (float*)d_out;
        attp = (float*)d_out + OUT_ELEMS;
    } else if (os >= ATT_ELEMS) {
        attp = (float*)d_out;
    } else {
        outp = (float*)d_out;
    }

    cvt_all<<<QK_BLOCKS + VF_BLOCKS + MBIT_BLOCKS, 256>>>(Q, K, V, M);

    cudaFuncSetAttribute(attn_kernel, cudaFuncAttributeMaxDynamicSharedMemorySize, SMEM_BYTES);
    dim3 grid(Ss / QT, BH);
    attn_kernel<<<grid, NTH, SMEM_BYTES>>>(outp, attp);
}

// round 17
// speedup vs baseline: 1.1844x; 1.1844x over previous
#include <cuda_runtime.h>
#include <cuda_fp16.h>
#include <cstdint>

#define Ss 2048
#define Dd 64
constexpr int BH  = 32;
constexpr int QT  = 64;            // q rows per CTA
constexpr int KT  = 128;           // k cols per tile
constexpr int NTH = 256;           // 8 warps: 4 row-groups x 2 col-halves
constexpr int NT  = Ss / KT;       // 16
constexpr long long OUT_ELEMS = (long long)BH * Ss * Dd;
constexpr long long ATT_ELEMS = (long long)BH * Ss * (long long)Ss;

// static device scratch
__device__ __align__(256) __half g_qh[(size_t)BH * Ss * Dd];   // pre-scaled by log2e/8
__device__ __align__(256) __half g_kh[(size_t)BH * Ss * Dd];
__device__ __align__(256) __half g_vh[(size_t)BH * Ss * Dd];
__device__ __align__(256) uint32_t g_mb[(size_t)2 * Ss * Ss / 32];   // bit-packed mask (1MB)
__device__ __align__(256) uint32_t g_u32[(size_t)ATT_ELEMS / 2];     // u relay, fragment layout

// smem layout (bytes)
constexpr int OFF_RED = 0;                        // srows[2][64] + srinv[64]
constexpr int OFF_Q   = 1024;                     // P1: 64 x 144 = 9216
constexpr int KSTG    = 128 * 144;                // 18432
constexpr int OFF_K   = 10240;                    // P1: 2 stages -> 47104
constexpr int OFF_V   = 1024;                     // P2 overlay: 2 stages -> 37888
constexpr int SMEM_BYTES = 47104;                 // 3 CTAs/SM

__device__ __forceinline__ uint32_t smem_u32(const void* p) {
    uint32_t a;
    asm("{ .reg .u64 t; cvta.to.shared.u64 t, %1; cvt.u32.u64 %0, t; }" : "=r"(a) : "l"(p));
    return a;
}
__device__ __forceinline__ void ldsm4(uint32_t r[4], uint32_t a) {
    asm volatile("ldmatrix.sync.aligned.m8n8.x4.shared.b16 {%0,%1,%2,%3}, [%4];"
                 : "=r"(r[0]), "=r"(r[1]), "=r"(r[2]), "=r"(r[3]) : "r"(a) : "memory");
}
__device__ __forceinline__ void ldsm4t(uint32_t r[4], uint32_t a) {
    asm volatile("ldmatrix.sync.aligned.m8n8.x4.trans.shared.b16 {%0,%1,%2,%3}, [%4];"
                 : "=r"(r[0]), "=r"(r[1]), "=r"(r[2]), "=r"(r[3]) : "r"(a) : "memory");
}
__device__ __forceinline__ void mma16816(float c[4], const uint32_t a[4], uint32_t b0, uint32_t b1) {
    asm volatile(
        "mma.sync.aligned.m16n8k16.row.col.f32.f16.f16.f32 "
        "{%0,%1,%2,%3}, {%4,%5,%6,%7}, {%8,%9}, {%0,%1,%2,%3};"
        : "+f"(c[0]), "+f"(c[1]), "+f"(c[2]), "+f"(c[3])
        : "r"(a[0]), "r"(a[1]), "r"(a[2]), "r"(a[3]), "r"(b0), "r"(b1));
}
__device__ __forceinline__ uint32_t packh2(float x, float y) {
    __half2 h = __floats2half2_rn(x, y);
    return *(uint32_t*)&h;
}
__device__ __forceinline__ float ex2f(float x) {
    float r; asm("ex2.approx.f32 %0, %1;" : "=f"(r) : "f"(x)); return r;
}
#define CPA16(dst, src) asm volatile("cp.async.cg.shared.global [%0], [%1], 16;" :: "r"(dst), "l"(src))
#define CP_COMMIT()     asm volatile("cp.async.commit_group;" ::: "memory")
#define CP_WAIT0()      asm volatile("cp.async.wait_group 0;" ::: "memory")
#define STG64CS(p, x, y) \
    asm volatile("st.global.cs.v2.f32 [%0], {%1,%2};" :: "l"(p), "f"(x), "f"(y) : "memory")
#define STG128CS(p, a, b, c, d) \
    asm volatile("st.global.cs.v4.b32 [%0], {%1,%2,%3,%4};" :: "l"(p), "r"(a), "r"(b), "r"(c), "r"(d) : "memory")
#define LDG128CS(r, p) \
    asm volatile("ld.global.cs.v4.b32 {%0,%1,%2,%3}, [%4];" \
                 : "=r"((r).x), "=r"((r).y), "=r"((r).z), "=r"((r).w) : "l"(p))

constexpr int QKV_BLOCKS  = 3 * (BH * Ss * Dd / 4) / 256;       // 12288
constexpr int MBIT_BLOCKS = (2 * Ss * Ss / 32) / 256;           // 1024
constexpr float QSCALE = 0.18033688011112042f;                  // log2(e)/8

__global__ void __launch_bounds__(256) cvt_all(const float* __restrict__ Q,
                                               const float* __restrict__ K,
                                               const float* __restrict__ V,
                                               const int* __restrict__ M)
{
    if (blockIdx.x < QKV_BLOCKS) {
        const int n4 = BH * Ss * Dd / 4;
        int id = blockIdx.x * 256 + threadIdx.x;
        const float* src; __half* dst; float s;
        int i = id;
        if (id < n4)          { src = Q; dst = g_qh; s = QSCALE; }
        else if (id < 2 * n4) { src = K; dst = g_kh; s = 1.f; i -= n4; }
        else                  { src = V; dst = g_vh; s = 1.f; i -= 2 * n4; }
        float4 v = ((const float4*)src)[i];
        uint2 u; u.x = packh2(v.x * s, v.y * s); u.y = packh2(v.z * s, v.w * s);
        ((uint2*)dst)[i] = u;
    } else {
        int gid = (blockIdx.x - QKV_BLOCKS) * 256 + threadIdx.x;
        const int4* mp = (const int4*)M + (size_t)gid * 8;
        uint32_t bits = 0;
        #pragma unroll
        for (int j = 0; j < 8; j++) {
            int4 m = mp[j];
            bits |= (m.x ? 1u : 0u) << (4 * j);
            bits |= (m.y ? 1u : 0u) << (4 * j + 1);
            bits |= (m.z ? 1u : 0u) << (4 * j + 2);
            bits |= (m.w ? 1u : 0u) << (4 * j + 3);
        }
        g_mb[gid] = bits;
    }
}

extern __shared__ __align__(16) char sm[];

// ---------------- pass 1 tile body ----------------
#define P1_BODY(T, CUR, NXT) do {                                          \
    if ((T) + 1 < NT) {                                                    \
        CPA16(kdst##NXT,         kpre);                                    \
        CPA16(kdst##NXT +  4608, kpre + 2048);                             \
        CPA16(kdst##NXT +  9216, kpre + 4096);                             \
        CPA16(kdst##NXT + 13824, kpre + 6144);                             \
        CP_COMMIT();                                                       \
        kpre += (size_t)KT * Dd;                                           \
        mn0 = __ldg(mr0 + 2 * ((T) + 1));                                  \
        mn1 = __ldg(mr1 + 2 * ((T) + 1));                                  \
    }                                                                      \
    _Pragma("unroll") for (int ch = 0; ch < 2; ch++) {                     \
        float c4[4][4];                                                    \
        _Pragma("unroll") for (int j = 0; j < 4; j++) {                    \
            c4[j][0] = 0.f; c4[j][1] = 0.f; c4[j][2] = 0.f; c4[j][3] = 0.f; } \
        _Pragma("unroll") for (int kc = 0; kc < 4; kc++)                   \
            _Pragma("unroll") for (int j = 0; j < 2; j++) {                \
                uint32_t bf[4];                                            \
                ldsm4(bf, kfr##CUR + (2 * ch + j) * 2304 + kc * 32);       \
                mma16816(c4[2 * j],     aQ[kc], bf[0], bf[1]);             \
                mma16816(c4[2 * j + 1], aQ[kc], bf[2], bf[3]);             \
            }                                                              \
        uint32_t ul[4], uh[4];                                             \
        _Pragma("unroll") for (int j = 0; j < 4; j++) {                    \
            const int p = 8 * (4 * ch + j) + 2 * tg;                       \
            uint32_t b0 = (uint32_t)(mc0 >> p), b1 = (uint32_t)(mc1 >> p); \
            float u0 = (b0 & 1u) ? ex2f(c4[j][0]) : 0.f;                   \
            float u1 = (b0 & 2u) ? ex2f(c4[j][1]) : 0.f;                   \
            float u2 = (b1 & 1u) ? ex2f(c4[j][2]) : 0.f;                   \
            float u3 = (b1 & 2u) ? ex2f(c4[j][3]) : 0.f;                   \
            rs0 += u0 + u1; rs1 += u2 + u3;                                \
            ul[j] = packh2(u0, u1); uh[j] = packh2(u2, u3);                \
        }                                                                  \
        STG128CS(ut + (2 * ch) * 1024,     ul[0], uh[0], ul[1], uh[1]);    \
        STG128CS(ut + (2 * ch + 1) * 1024, ul[2], uh[2], ul[3], uh[3]);    \
    }                                                                      \
    ut += 4096;                                                            \
    mc0 = mn0; mc1 = mn1;                                                  \
    if ((T) + 1 < NT) { CP_WAIT0(); __syncthreads(); }                     \
} while (0)

// ---------------- pass 2 tile body (u via direct LDG.128.cs, frag layout) ----------------
#define P2_BODY(T, CUR, NXT) do {                                          \
    uint4 ua[4];                                                           \
    LDG128CS(ua[0], upr);                                                  \
    LDG128CS(ua[1], upr + 4096);                                           \
    LDG128CS(ua[2], upr + 8192);                                           \
    LDG128CS(ua[3], upr + 12288);                                          \
    upr += 16384;                                                          \
    if ((T) + 1 < NT) {                                                    \
        CPA16(vdst##NXT,         vpre);                                    \
        CPA16(vdst##NXT +  4608, vpre + 2048);                             \
        CPA16(vdst##NXT +  9216, vpre + 4096);                             \
        CPA16(vdst##NXT + 13824, vpre + 6144);                             \
        CP_COMMIT();                                                       \
        vpre += (size_t)KT * Dd;                                           \
    }                                                                      \
    _Pragma("unroll") for (int kc = 0; kc < 4; kc++) {                     \
        uint32_t a[4] = { ua[kc].x, ua[kc].y, ua[kc].z, ua[kc].w };        \
        _Pragma("unroll") for (int np = 0; np < 4; np++) {                 \
            uint32_t bf[4];                                                \
            ldsm4t(bf, vfr##CUR + kc * 2304 + np * 32);                    \
            mma16816(o[2 * np],     a, bf[0], bf[1]);                      \
            mma16816(o[2 * np + 1], a, bf[2], bf[3]);                      \
        }                                                                  \
        if (ar) {                                                          \
            float2 f0 = __half22float2(*(__half2*)&a[0]);                  \
            float2 f1 = __half22float2(*(__half2*)&a[1]);                  \
            float2 f2 = __half22float2(*(__half2*)&a[2]);                  \
            float2 f3 = __half22float2(*(__half2*)&a[3]);                  \
            STG64CS(ar + 16 * kc,              f0.x * rv0, f0.y * rv0);    \
            STG64CS(ar + 8 * Ss + 16 * kc,     f1.x * rv1, f1.y * rv1);    \
            STG64CS(ar + 16 * kc + 8,          f2.x * rv0, f2.y * rv0);    \
            STG64CS(ar + 8 * Ss + 16 * kc + 8, f3.x * rv1, f3.y * rv1);    \
        }                                                                  \
    }                                                                      \
    if (ar) ar += KT;                                                      \
    if ((T) + 1 < NT) { CP_WAIT0(); __syncthreads(); }                     \
} while (0)

__global__ void __launch_bounds__(NTH, 3)
attn_kernel(float* __restrict__ out, float* __restrict__ att)
{
    const int tid  = threadIdx.x;
    const int lane = tid & 31;
    const int warp = tid >> 5;
    const int g    = lane >> 2;
    const int tg   = lane & 3;
    const int lm   = lane >> 3;
    const int ll   = lane & 7;
    const int rgrp = warp & 3;         // q-row group (16 rows)
    const int h    = warp >> 2;        // k-col half (64 cols)

    const int qblk = blockIdx.x;
    const int q0 = qblk * QT;
    const int bh = blockIdx.y;
    const int b  = bh >> 4;

    const uint32_t smb = smem_u32(sm);
    float* srows = (float*)(sm + OFF_RED);          // [2][64]
    float* srinv = (float*)(sm + OFF_RED + 512);    // [64]

    const __half* qsrc = g_qh + ((size_t)bh * Ss + q0) * Dd;
    const __half* ksrc = g_kh + (size_t)bh * Ss * Dd;
    const __half* vsrc = g_vh + (size_t)bh * Ss * Dd;
    float* attg = att ? (att + (size_t)bh * Ss * (size_t)Ss) : nullptr;

    const int r0 = rgrp * 16 + g;
    const int r1 = r0 + 8;

    // bit-mask row pointers (u64 per 64 cols; row stride = 32 u64)
    const unsigned long long* mb64 = (const unsigned long long*)g_mb;
    const unsigned long long* mr0 = mb64 + ((size_t)b * Ss + q0 + r0) * 32 + h;
    const unsigned long long* mr1 = mr0 + 8 * 32;

    // u relay pointers (fragment layout: [tile][slot(4)][tid][16B])
    uint32_t* ut = g_u32 + (((size_t)bh * 32 + qblk) * 16) * 4096 + tid * 4;
    const char* upr = (const char*)(g_u32 + (((size_t)bh * 32 + qblk) * 16) * 4096) + tid * 16;

    // per-thread cp.async addresses
    const int lr_ = tid >> 3, lc = tid & 7;          // K/V pattern: 32 rows x 8 chunks
    const uint32_t kdstA = smb + OFF_K + lr_ * 144 + lc * 16;
    const uint32_t kdstB = kdstA + KSTG;
    const uint32_t vdstA = smb + OFF_V + lr_ * 144 + lc * 16;
    const uint32_t vdstB = vdstA + KSTG;
    const __half* ksrcT = ksrc + lr_ * 64 + lc * 8;
    const __half* vsrcT = vsrc + lr_ * 64 + lc * 8;

    // fragment bases
    const uint32_t qfr  = smb + OFF_Q + (uint32_t)((rgrp * 16 + (lm & 1) * 8 + ll) * 144 + (lm >> 1) * 16);
    const uint32_t kfrA = smb + OFF_K + (uint32_t)((h * 64 + (lm >> 1) * 8 + ll) * 144 + (lm & 1) * 16);
    const uint32_t kfrB = kfrA + KSTG;
    const uint32_t vfrA = smb + OFF_V + (uint32_t)((h * 64 + (lm & 1) * 8 + ll) * 144 + (lm >> 1) * 16);
    const uint32_t vfrB = vfrA + KSTG;

    // ---- pass-1 prologue: Q + K0 ----
    CPA16(smb + OFF_Q + lr_ * 144 + lc * 16, qsrc + lr_ * 64 + lc * 8);
    CPA16(smb + OFF_Q + (lr_ + 32) * 144 + lc * 16, qsrc + (lr_ + 32) * 64 + lc * 8);
    CPA16(kdstA,         ksrcT);
    CPA16(kdstA +  4608, ksrcT + 2048);
    CPA16(kdstA +  9216, ksrcT + 4096);
    CPA16(kdstA + 13824, ksrcT + 6144);
    CP_COMMIT();
    unsigned long long mc0 = __ldg(mr0), mc1 = __ldg(mr1), mn0 = 0, mn1 = 0;
    CP_WAIT0(); __syncthreads();

    uint32_t aQ[4][4];
    #pragma unroll
    for (int kc = 0; kc < 4; kc++) ldsm4(aQ[kc], qfr + kc * 32);

    // ================= PASS 1: row sums + u relay store =================
    float rs0 = 0.f, rs1 = 0.f;
    {
        const __half* kpre = ksrcT + (size_t)KT * Dd;
        #pragma unroll 1
        for (int t2 = 0; t2 < NT; t2 += 2) {
            P1_BODY(t2,     A, B);
            P1_BODY(t2 + 1, B, A);
        }
    }

    // reduce quad lanes, then the 2 col-halves; reciprocals
    rs0 += __shfl_xor_sync(0xffffffffu, rs0, 1); rs0 += __shfl_xor_sync(0xffffffffu, rs0, 2);
    rs1 += __shfl_xor_sync(0xffffffffu, rs1, 1); rs1 += __shfl_xor_sync(0xffffffffu, rs1, 2);
    if (tg == 0) { srows[h * 64 + r0] = rs0; srows[h * 64 + r1] = rs1; }
    __syncthreads();
    if (tid < 64) {
        float s = srows[tid] + srows[64 + tid];
        srinv[tid] = (s > 0.f) ? (1.0f / s) : 0.f;
    }
    __syncthreads();
    const float rv0 = srinv[r0];
    const float rv1 = srinv[r1];
    __syncthreads();          // all reads of reduction smem done before V overlays it

    // ================= PASS 2: PV + scaled att writeout =================
    float o[8][4];
    #pragma unroll
    for (int j = 0; j < 8; j++) { o[j][0] = 0.f; o[j][1] = 0.f; o[j][2] = 0.f; o[j][3] = 0.f; }

    // prologue: V0 -> stage A
    CPA16(vdstA,         vsrcT);
    CPA16(vdstA +  4608, vsrcT + 2048);
    CPA16(vdstA +  9216, vsrcT + 4096);
    CPA16(vdstA + 13824, vsrcT + 6144);
    CP_COMMIT(); CP_WAIT0(); __syncthreads();

    {
        const __half* vpre = vsrcT + (size_t)KT * Dd;
        float* ar = attg ? (attg + (size_t)(q0 + r0) * Ss + h * 64 + 2 * tg) : nullptr;
        #pragma unroll 1
        for (int t2 = 0; t2 < NT; t2 += 2) {
            P2_BODY(t2,     A, B);
            P2_BODY(t2 + 1, B, A);
        }
    }

    // ---- combine the two k-halves of O via smem, scale by rinv, write ----
    __syncthreads();
    float* ost = (float*)(sm + OFF_V);            // [64][66]
    if (h == 1) {
        #pragma unroll
        for (int j = 0; j < 8; j++) {
            *(float2*)&ost[r0 * 66 + 8 * j + 2 * tg] = make_float2(o[j][0], o[j][1]);
            *(float2*)&ost[r1 * 66 + 8 * j + 2 * tg] = make_float2(o[j][2], o[j][3]);
        }
    }
    __syncthreads();
    if (out && h == 0) {
        float* og0 = out + ((size_t)bh * Ss + q0 + r0) * Dd;
        float* og1 = out + ((size_t)bh * Ss + q0 + r1) * Dd;
        #pragma unroll
        for (int j = 0; j < 8; j++) {
            float2 s0 = *(float2*)&ost[r0 * 66 + 8 * j + 2 * tg];
            float2 s1 = *(float2*)&ost[r1 * 66 + 8 * j + 2 * tg];
            *(float2*)(og0 + 8 * j + 2 * tg) = make_float2((o[j][0] + s0.x) * rv0, (o[j][1] + s0.y) * rv0);
            *(float2*)(og1 + 8 * j + 2 * tg) = make_float2((o[j][2] + s1.x) * rv1, (o[j][3] + s1.y) * rv1);
        }
    }
}

extern "C" void kernel_launch(void* const* d_in, const int* in_sizes, int n_in,
                              void* d_out, int out_size)
{
    (void)in_sizes; (void)n_in;
    const float* Q = (const float*)d_in[0];
    const float* K = (const float*)d_in[1];
    const float* V = (const float*)d_in[2];
    const int*   M = (const int*)d_in[3];

    float* outp = nullptr;
    float* attp = nullptr;
    long long os = (long long)out_size;
    if (os >= OUT_ELEMS + ATT_ELEMS) {
        outp = (float*)d_out;
        attp = (float*)d_out + OUT_ELEMS;
    } else if (os >= ATT_ELEMS) {
        attp = (float*)d_out;
    } else {
        outp = (float*)d_out;
    }

    cvt_all<<<QKV_BLOCKS + MBIT_BLOCKS, 256>>>(Q, K, V, M);

    cudaFuncSetAttribute(attn_kernel, cudaFuncAttributeMaxDynamicSharedMemorySize, SMEM_BYTES);
    dim3 grid(Ss / QT, BH);
    attn_kernel<<<grid, NTH, SMEM_BYTES>>>(outp, attp);
}